// round 1
// baseline (speedup 1.0000x reference)
#include <cuda_runtime.h>

// Problem constants (fixed shapes from reference setup_inputs)
#define CDIM 3755
#define RDIM 214
#define SDIM 13
#define SCBDIM 30
#define STDIM 6
#define HDIM 64
#define KTOP 20
#define NBINS 4096
#define CAP 256
#define NT 256

__device__ __forceinline__ unsigned f2key(float x) {
    unsigned u = __float_as_uint(x);
    return (u & 0x80000000u) ? ~u : (u | 0x80000000u);
}

__global__ void __launch_bounds__(NT) rerank_kernel(
    const float* __restrict__ charL,   // (B, C)
    const float* __restrict__ radL,    // (B, R)
    const float* __restrict__ structL, // (B, S)
    const float* __restrict__ scL,     // (B, SCB)
    const float* __restrict__ styL,    // (B, ST)
    const int*   __restrict__ rmask,   // (C, R)
    const int*   __restrict__ slab,    // (C,)
    const int*   __restrict__ sclab,   // (C,)
    const float* __restrict__ sig,     // (C, ST)
    const float* __restrict__ W1,      // (6, H)
    const float* __restrict__ b1,      // (H,)
    const float* __restrict__ W2,      // (H, 1)
    const float* __restrict__ b2,      // (1,)
    const float* __restrict__ rw,      // scalar
    float* __restrict__ out)           // (B, C)
{
    __shared__ float logits[CDIM];
    __shared__ unsigned hist[NBINS];
    __shared__ float rprobs[RDIM];
    __shared__ float sprobs[SDIM];
    __shared__ float w1s[6 * HDIM];
    __shared__ float b1s[HDIM];
    __shared__ float w2s[HDIM];
    __shared__ unsigned ckey[CAP];
    __shared__ int cidxs[CAP];
    __shared__ int topIdx[KTOP];
    __shared__ float topVal[KTOP];
    __shared__ float comb[KTOP];
    __shared__ float red[NT / 32];
    __shared__ float red2[NT / 32];
    __shared__ unsigned long long red64[NT / 32];
    __shared__ unsigned suf[NT];
    __shared__ float s_max, s_sum, s_total, s_b2, s_rw;
    __shared__ float s_predn[STDIM];
    __shared__ int s_spred;
    __shared__ unsigned s_bt;
    __shared__ int s_ncand;

    const int b = blockIdx.x;
    const int tid = threadIdx.x;
    const int lane = tid & 31;
    const int wid = tid >> 5;

    // ---- Phase A: init ----
    for (int i = tid; i < NBINS; i += NT) hist[i] = 0u;
    if (tid == 0) s_ncand = 0;
    for (int i = tid; i < 6 * HDIM; i += NT) w1s[i] = W1[i];
    if (tid < HDIM) { b1s[tid] = b1[tid]; w2s[tid] = W2[tid]; }
    if (tid == 0) { s_b2 = b2[0]; s_rw = rw[0]; }
    __syncthreads();

    // ---- Phase B: load logits row -> smem, histogram, row max ----
    const float* row = charL + (size_t)b * CDIM;
    float lmax = -3.4e38f;
    for (int j = tid; j < CDIM; j += NT) {
        float v = row[j];
        logits[j] = v;
        atomicAdd(&hist[f2key(v) >> 20], 1u);
        lmax = fmaxf(lmax, v);
    }
    #pragma unroll
    for (int o = 16; o; o >>= 1) lmax = fmaxf(lmax, __shfl_down_sync(0xffffffffu, lmax, o));
    if (lane == 0) red[wid] = lmax;

    // independent small per-row tasks on distinct threads (different warps)
    if (tid == 33) { // structure softmax
        const float* st = structL + (size_t)b * SDIM;
        float m = st[0];
        float e[SDIM];
        for (int i = 1; i < SDIM; i++) m = fmaxf(m, st[i]);
        float s = 0.f;
        for (int i = 0; i < SDIM; i++) { e[i] = __expf(st[i] - m); s += e[i]; }
        float inv = 1.f / s;
        for (int i = 0; i < SDIM; i++) sprobs[i] = e[i] * inv;
    }
    if (tid == 65) { // stroke count argmax (first max index)
        const float* sc = scL + (size_t)b * SCBDIM;
        float m = sc[0]; int mi = 0;
        for (int i = 1; i < SCBDIM; i++) { float v = sc[i]; if (v > m) { m = v; mi = i; } }
        s_spred = mi;
    }
    if (tid == 97) { // normalized stroke-type prediction
        const float* sy = styL + (size_t)b * STDIM;
        float v[STDIM]; float n2 = 0.f;
        for (int i = 0; i < STDIM; i++) { v[i] = sy[i]; n2 += v[i] * v[i]; }
        float n = fmaxf(sqrtf(n2), 1e-12f);
        for (int i = 0; i < STDIM; i++) s_predn[i] = v[i] / n;
    }
    __syncthreads();
    if (tid == 0) {
        float m = red[0];
        for (int w = 1; w < NT / 32; w++) m = fmaxf(m, red[w]);
        s_max = m;
    }
    __syncthreads();
    const float rowmax = s_max;

    // ---- Phase C: softmax denominator + radical sigmoid/total ----
    float se = 0.f;
    for (int j = tid; j < CDIM; j += NT) se += __expf(logits[j] - rowmax);
    #pragma unroll
    for (int o = 16; o; o >>= 1) se += __shfl_down_sync(0xffffffffu, se, o);
    if (lane == 0) red[wid] = se;

    float tp = 0.f;
    for (int r = tid; r < RDIM; r += NT) {
        float p = 1.f / (1.f + __expf(-radL[(size_t)b * RDIM + r]));
        rprobs[r] = p;
        tp += p;
    }
    #pragma unroll
    for (int o = 16; o; o >>= 1) tp += __shfl_down_sync(0xffffffffu, tp, o);
    if (lane == 0) red2[wid] = tp;
    __syncthreads();
    if (tid == 0) {
        float s = 0.f, t = 0.f;
        for (int w = 0; w < NT / 32; w++) { s += red[w]; t += red2[w]; }
        s_sum = s; s_total = t;
    }

    // ---- Phase D: suffix scan over histogram to find top-K cutoff bin ----
    unsigned csum = 0;
    {
        const int base = tid * (NBINS / NT);
        #pragma unroll
        for (int i = 0; i < NBINS / NT; i++) csum += hist[base + i];
    }
    suf[tid] = csum;
    __syncthreads();
    for (int off = 1; off < NT; off <<= 1) {
        unsigned v = (tid + off < NT) ? suf[tid + off] : 0u;
        __syncthreads();
        suf[tid] += v;
        __syncthreads();
    }
    if (suf[tid] >= KTOP && (tid == NT - 1 || suf[tid + 1] < KTOP)) {
        unsigned cnt = (tid < NT - 1) ? suf[tid + 1] : 0u;
        const int base = tid * (NBINS / NT);
        for (int bin = base + NBINS / NT - 1; bin >= base; bin--) {
            cnt += hist[bin];
            if (cnt >= KTOP) { s_bt = (unsigned)bin; break; }
        }
    }
    __syncthreads();
    const unsigned bt = s_bt;

    // ---- Phase E: collect candidates >= cutoff bin ----
    for (int j = tid; j < CDIM; j += NT) {
        unsigned key = f2key(logits[j]);
        if ((key >> 20) >= bt) {
            int p = atomicAdd(&s_ncand, 1);
            if (p < CAP) { ckey[p] = key; cidxs[p] = j; }
        }
    }
    __syncthreads();
    const int ncand = s_ncand;

    if (ncand <= CAP) {
        // exact top-K among candidates; tie-break = lower index (matches lax.top_k)
        if (wid == 0) {
            for (int k = 0; k < KTOP; k++) {
                unsigned long long best = 0ull;
                for (int i = lane; i < ncand; i += 32) {
                    unsigned long long p = ((unsigned long long)ckey[i] << 32)
                                         | (unsigned)(0x7FFFFFFF - cidxs[i]);
                    if (p > best) best = p;
                }
                #pragma unroll
                for (int o = 16; o; o >>= 1) {
                    unsigned long long q = __shfl_down_sync(0xffffffffu, best, o);
                    if (q > best) best = q;
                }
                best = __shfl_sync(0xffffffffu, best, 0);
                if (lane == 0) {
                    int idx = 0x7FFFFFFF - (int)(best & 0xFFFFFFFFu);
                    topIdx[k] = idx;
                    topVal[k] = logits[idx];
                }
                for (int i = lane; i < ncand; i += 32) {
                    unsigned long long p = ((unsigned long long)ckey[i] << 32)
                                         | (unsigned)(0x7FFFFFFF - cidxs[i]);
                    if (p == best) ckey[i] = 0u; // mark consumed
                }
            }
        }
        __syncthreads();
    } else {
        // robust fallback: iterative block argmax (never expected on this data)
        for (int k = 0; k < KTOP; k++) {
            unsigned long long best = 0ull;
            for (int j = tid; j < CDIM; j += NT) {
                unsigned long long p = ((unsigned long long)f2key(logits[j]) << 32)
                                     | (unsigned)(0x7FFFFFFF - j);
                if (p > best) best = p;
            }
            #pragma unroll
            for (int o = 16; o; o >>= 1) {
                unsigned long long q = __shfl_down_sync(0xffffffffu, best, o);
                if (q > best) best = q;
            }
            if (lane == 0) red64[wid] = best;
            __syncthreads();
            if (tid == 0) {
                unsigned long long m = red64[0];
                for (int w = 1; w < NT / 32; w++) if (red64[w] > m) m = red64[w];
                int idx = 0x7FFFFFFF - (int)(m & 0xFFFFFFFFu);
                topIdx[k] = idx;
                topVal[k] = logits[idx];
                logits[idx] = -3.4e38f; // exclude; overwritten by scatter later
            }
            __syncthreads();
        }
    }

    // ---- Phase F: features + MLP, one warp per candidate ----
    const float inv_sum = 1.f / s_sum;
    const float total = s_total;
    const float totden = 1.f / fmaxf(total, 1e-6f);

    for (int k = wid; k < KTOP; k += NT / 32) {
        const int c = topIdx[k];
        float det = 0.f; int cnt = 0;
        const int* mrow = rmask + (size_t)c * RDIM;
        for (int r = lane; r < RDIM; r += 32) {
            int m = mrow[r];
            if (m) det += rprobs[r];
            cnt += m;
        }
        #pragma unroll
        for (int o = 16; o; o >>= 1) {
            det += __shfl_down_sync(0xffffffffu, det, o);
            cnt += __shfl_down_sync(0xffffffffu, cnt, o);
        }
        float f0 = 0.f, f1 = 0.f, f2 = 0.f, f3 = 0.f, f4 = 0.f, f5 = 0.f;
        if (lane == 0) {
            float cc = fmaxf((float)cnt, 1.f);
            f0 = det / cc;                       // radical match ratio
            f1 = (total - det) * totden;         // radical false-alarm ratio
            f2 = sprobs[slab[c]];                // structure match
            f3 = fabsf((float)(s_spred - sclab[c])) * (1.f / 29.f); // stroke distance
            float sv[STDIM]; float n2 = 0.f;
            for (int i = 0; i < STDIM; i++) { sv[i] = sig[(size_t)c * STDIM + i]; n2 += sv[i] * sv[i]; }
            float nrm = sqrtf(n2);
            if (nrm > 1e-6f) {
                float inv = 1.f / fmaxf(nrm, 1e-12f);
                float d = 0.f;
                for (int i = 0; i < STDIM; i++) d += s_predn[i] * sv[i];
                f4 = d * inv;                    // stroke-type cosine
            }
            f5 = __expf(topVal[k] - rowmax) * inv_sum; // neural confidence
        }
        f0 = __shfl_sync(0xffffffffu, f0, 0);
        f1 = __shfl_sync(0xffffffffu, f1, 0);
        f2 = __shfl_sync(0xffffffffu, f2, 0);
        f3 = __shfl_sync(0xffffffffu, f3, 0);
        f4 = __shfl_sync(0xffffffffu, f4, 0);
        f5 = __shfl_sync(0xffffffffu, f5, 0);

        // MLP: 2 hidden units per lane
        float score = 0.f;
        #pragma unroll
        for (int u = 0; u < 2; u++) {
            int j = lane + u * 32;
            float h = b1s[j] + f0 * w1s[0 * HDIM + j] + f1 * w1s[1 * HDIM + j]
                            + f2 * w1s[2 * HDIM + j] + f3 * w1s[3 * HDIM + j]
                            + f4 * w1s[4 * HDIM + j] + f5 * w1s[5 * HDIM + j];
            score += fmaxf(h, 0.f) * w2s[j];
        }
        #pragma unroll
        for (int o = 16; o; o >>= 1) score += __shfl_down_sync(0xffffffffu, score, o);
        if (lane == 0) comb[k] = topVal[k] + s_rw * (score + s_b2);
    }
    __syncthreads();

    // ---- Phase G: scatter combined scores, stream row out ----
    if (tid < KTOP) logits[topIdx[tid]] = comb[tid];
    __syncthreads();
    float* orow = out + (size_t)b * CDIM;
    for (int j = tid; j < CDIM; j += NT) orow[j] = logits[j];
}

extern "C" void kernel_launch(void* const* d_in, const int* in_sizes, int n_in,
                              void* d_out, int out_size) {
    (void)n_in; (void)out_size;
    int Bn = in_sizes[0] / CDIM;
    rerank_kernel<<<Bn, NT>>>(
        (const float*)d_in[0],  (const float*)d_in[1],  (const float*)d_in[2],
        (const float*)d_in[3],  (const float*)d_in[4],  (const int*)d_in[5],
        (const int*)d_in[6],    (const int*)d_in[7],    (const float*)d_in[8],
        (const float*)d_in[9],  (const float*)d_in[10], (const float*)d_in[11],
        (const float*)d_in[12], (const float*)d_in[13], (float*)d_out);
}

// round 2
// speedup vs baseline: 1.2138x; 1.2138x over previous
#include <cuda_runtime.h>

// Problem constants (fixed shapes from reference setup_inputs)
#define CDIM 3755
#define RDIM 214
#define SDIM 13
#define SCBDIM 30
#define STDIM 6
#define HDIM 64
#define KTOP 20
#define CAP 256
#define NT 256

__device__ __forceinline__ unsigned f2key(float x) {
    unsigned u = __float_as_uint(x);
    return (u & 0x80000000u) ? ~u : (u | 0x80000000u);
}

__global__ void __launch_bounds__(NT) rerank_kernel(
    const float* __restrict__ charL,   // (B, C)
    const float* __restrict__ radL,    // (B, R)
    const float* __restrict__ structL, // (B, S)
    const float* __restrict__ scL,     // (B, SCB)
    const float* __restrict__ styL,    // (B, ST)
    const int*   __restrict__ rmask,   // (C, R)
    const int*   __restrict__ slab,    // (C,)
    const int*   __restrict__ sclab,   // (C,)
    const float* __restrict__ sig,     // (C, ST)
    const float* __restrict__ W1,      // (6, H)
    const float* __restrict__ b1,      // (H,)
    const float* __restrict__ W2,      // (H, 1)
    const float* __restrict__ b2,      // (1,)
    const float* __restrict__ rw,      // scalar
    float* __restrict__ out)           // (B, C)
{
    __shared__ float logits[CDIM];
    __shared__ float rprobs[RDIM];
    __shared__ float sprobs[SDIM];
    __shared__ float w1s[6 * HDIM];
    __shared__ float b1s[HDIM];
    __shared__ float w2s[HDIM];
    __shared__ unsigned ckey[CAP];
    __shared__ int cidxs[CAP];
    __shared__ int topIdx[KTOP];
    __shared__ float topVal[KTOP];
    __shared__ float comb[KTOP];
    __shared__ float feat[KTOP][6];
    __shared__ float red[NT / 32];
    __shared__ float red2[NT / 32];
    __shared__ unsigned long long red64[NT / 32];
    __shared__ float s_max, s_sum, s_total, s_b2, s_rw;
    __shared__ float s_predn[STDIM];
    __shared__ int s_spred;
    __shared__ int s_ncand;

    const int b = blockIdx.x;
    const int tid = threadIdx.x;
    const int lane = tid & 31;
    const int wid = tid >> 5;

    // ---- Phase A: stage weights ----
    for (int i = tid; i < 6 * HDIM; i += NT) w1s[i] = W1[i];
    if (tid < HDIM) { b1s[tid] = b1[tid]; w2s[tid] = W2[tid]; }
    if (tid == 0) { s_b2 = b2[0]; s_rw = rw[0]; }

    // ---- Phase B: global -> smem + row max; small per-row side tasks ----
    const float* row = charL + (size_t)b * CDIM;
    float lmax = -3.4e38f;
    for (int j = tid; j < CDIM; j += NT) {
        float v = row[j];
        logits[j] = v;
        lmax = fmaxf(lmax, v);
    }
    #pragma unroll
    for (int o = 16; o; o >>= 1) lmax = fmaxf(lmax, __shfl_down_sync(0xffffffffu, lmax, o));
    if (lane == 0) red[wid] = lmax;

    if (tid == 33) { // structure softmax
        const float* st = structL + (size_t)b * SDIM;
        float m = st[0];
        float e[SDIM];
        for (int i = 1; i < SDIM; i++) m = fmaxf(m, st[i]);
        float s = 0.f;
        for (int i = 0; i < SDIM; i++) { e[i] = __expf(st[i] - m); s += e[i]; }
        float inv = 1.f / s;
        for (int i = 0; i < SDIM; i++) sprobs[i] = e[i] * inv;
    }
    if (tid == 65) { // stroke count argmax (first max index)
        const float* sc = scL + (size_t)b * SCBDIM;
        float m = sc[0]; int mi = 0;
        for (int i = 1; i < SCBDIM; i++) { float v = sc[i]; if (v > m) { m = v; mi = i; } }
        s_spred = mi;
    }
    if (tid == 97) { // normalized stroke-type prediction
        const float* sy = styL + (size_t)b * STDIM;
        float v[STDIM]; float n2 = 0.f;
        for (int i = 0; i < STDIM; i++) { v[i] = sy[i]; n2 += v[i] * v[i]; }
        float n = fmaxf(sqrtf(n2), 1e-12f);
        for (int i = 0; i < STDIM; i++) s_predn[i] = v[i] / n;
    }
    __syncthreads();
    if (tid == 0) {
        float m = red[0];
        for (int w = 1; w < NT / 32; w++) m = fmaxf(m, red[w]);
        s_max = m;
    }
    __syncthreads();
    const float rowmax = s_max;

    // ---- Phase C: softmax denominator + radical sigmoid/total ----
    float se = 0.f;
    for (int j = tid; j < CDIM; j += NT) se += __expf(logits[j] - rowmax);
    #pragma unroll
    for (int o = 16; o; o >>= 1) se += __shfl_down_sync(0xffffffffu, se, o);
    if (lane == 0) red[wid] = se;

    float tp = 0.f;
    for (int r = tid; r < RDIM; r += NT) {
        float p = 1.f / (1.f + __expf(-radL[(size_t)b * RDIM + r]));
        rprobs[r] = p;
        tp += p;
    }
    #pragma unroll
    for (int o = 16; o; o >>= 1) tp += __shfl_down_sync(0xffffffffu, tp, o);
    if (lane == 0) red2[wid] = tp;
    __syncthreads();
    if (tid == 0) {
        float s = 0.f, t = 0.f;
        for (int w = 0; w < NT / 32; w++) { s += red[w]; t += red2[w]; }
        s_sum = s; s_total = t;
    }

    // ---- Phase D: threshold-based candidate collection (no histogram) ----
    float d = 1.25f;
    int ncand;
    for (;;) {
        __syncthreads();
        if (tid == 0) s_ncand = 0;
        __syncthreads();
        const float t = rowmax - d;
        for (int j = tid; j < CDIM; j += NT) {
            float v = logits[j];
            if (v >= t) {
                int p = atomicAdd(&s_ncand, 1);
                if (p < CAP) { ckey[p] = f2key(v); cidxs[p] = j; }
            }
        }
        __syncthreads();
        ncand = s_ncand;
        if (ncand >= KTOP) break;
        d *= 1.5f;   // grows until t -> -inf; guarantees termination
    }

    // ---- Phase E: exact top-K selection (tie-break: lower index first) ----
    if (ncand <= CAP) {
        if (wid == 0) {
            for (int k = 0; k < KTOP; k++) {
                unsigned long long best = 0ull;
                for (int i = lane; i < ncand; i += 32) {
                    unsigned long long p = ((unsigned long long)ckey[i] << 32)
                                         | (unsigned)(0x7FFFFFFF - cidxs[i]);
                    if (p > best) best = p;
                }
                #pragma unroll
                for (int o = 16; o; o >>= 1) {
                    unsigned long long q = __shfl_down_sync(0xffffffffu, best, o);
                    if (q > best) best = q;
                }
                best = __shfl_sync(0xffffffffu, best, 0);
                if (lane == 0) {
                    int idx = 0x7FFFFFFF - (int)(best & 0xFFFFFFFFu);
                    topIdx[k] = idx;
                    topVal[k] = logits[idx];
                }
                for (int i = lane; i < ncand; i += 32) {
                    unsigned long long p = ((unsigned long long)ckey[i] << 32)
                                         | (unsigned)(0x7FFFFFFF - cidxs[i]);
                    if (p == best) ckey[i] = 0u; // consumed
                }
            }
        }
        __syncthreads();
    } else {
        // robust fallback: iterative block argmax (adversarial data only)
        for (int k = 0; k < KTOP; k++) {
            unsigned long long best = 0ull;
            for (int j = tid; j < CDIM; j += NT) {
                unsigned long long p = ((unsigned long long)f2key(logits[j]) << 32)
                                     | (unsigned)(0x7FFFFFFF - j);
                if (p > best) best = p;
            }
            #pragma unroll
            for (int o = 16; o; o >>= 1) {
                unsigned long long q = __shfl_down_sync(0xffffffffu, best, o);
                if (q > best) best = q;
            }
            if (lane == 0) red64[wid] = best;
            __syncthreads();
            if (tid == 0) {
                unsigned long long m = red64[0];
                for (int w = 1; w < NT / 32; w++) if (red64[w] > m) m = red64[w];
                int idx = 0x7FFFFFFF - (int)(m & 0xFFFFFFFFu);
                topIdx[k] = idx;
                topVal[k] = logits[idx];
                logits[idx] = -3.4e38f; // excluded; overwritten by scatter later
            }
            __syncthreads();
        }
    }

    // ---- Phase F1: radical dot + count, one warp per candidate ----
    const float total = s_total;
    const float totden = 1.f / fmaxf(total, 1e-6f);
    for (int k = wid; k < KTOP; k += NT / 32) {
        const int c = topIdx[k];
        float det = 0.f; int cnt = 0;
        const int* mrow = rmask + (size_t)c * RDIM;
        for (int r = lane; r < RDIM; r += 32) {
            int m = mrow[r];
            if (m) det += rprobs[r];
            cnt += m;
        }
        #pragma unroll
        for (int o = 16; o; o >>= 1) {
            det += __shfl_down_sync(0xffffffffu, det, o);
            cnt += __shfl_down_sync(0xffffffffu, cnt, o);
        }
        if (lane == 0) {
            feat[k][0] = det / fmaxf((float)cnt, 1.f);   // radical match ratio
            feat[k][1] = (total - det) * totden;          // radical false-alarm ratio
        }
    }

    // ---- Phase F2: scalar features, one thread per candidate ----
    const float inv_sum = 1.f / s_sum;
    if (tid < KTOP) {
        const int c = topIdx[tid];
        feat[tid][2] = sprobs[slab[c]];                                   // structure match
        feat[tid][3] = fabsf((float)(s_spred - sclab[c])) * (1.f / 29.f); // stroke distance
        float sv[STDIM]; float n2 = 0.f;
        #pragma unroll
        for (int i = 0; i < STDIM; i++) { sv[i] = sig[(size_t)c * STDIM + i]; n2 += sv[i] * sv[i]; }
        float nrm = sqrtf(n2);
        float f4 = 0.f;
        if (nrm > 1e-6f) {
            float inv = 1.f / fmaxf(nrm, 1e-12f);
            float dd = 0.f;
            #pragma unroll
            for (int i = 0; i < STDIM; i++) dd += s_predn[i] * sv[i];
            f4 = dd * inv;                                                // stroke-type cosine
        }
        feat[tid][4] = f4;
        feat[tid][5] = __expf(topVal[tid] - rowmax) * inv_sum;            // neural confidence
    }
    __syncthreads();

    // ---- Phase F3: MLP 6->64->1, one warp per candidate, 2 units/lane ----
    for (int k = wid; k < KTOP; k += NT / 32) {
        float f0 = feat[k][0], f1 = feat[k][1], f2 = feat[k][2];
        float f3 = feat[k][3], f4 = feat[k][4], f5 = feat[k][5];
        float score = 0.f;
        #pragma unroll
        for (int u = 0; u < 2; u++) {
            int j = lane + u * 32;
            float h = b1s[j] + f0 * w1s[0 * HDIM + j] + f1 * w1s[1 * HDIM + j]
                            + f2 * w1s[2 * HDIM + j] + f3 * w1s[3 * HDIM + j]
                            + f4 * w1s[4 * HDIM + j] + f5 * w1s[5 * HDIM + j];
            score += fmaxf(h, 0.f) * w2s[j];
        }
        #pragma unroll
        for (int o = 16; o; o >>= 1) score += __shfl_down_sync(0xffffffffu, score, o);
        if (lane == 0) comb[k] = topVal[k] + s_rw * (score + s_b2);
    }
    __syncthreads();

    // ---- Phase G: scatter combined scores, stream row out ----
    if (tid < KTOP) logits[topIdx[tid]] = comb[tid];
    __syncthreads();
    float* orow = out + (size_t)b * CDIM;
    for (int j = tid; j < CDIM; j += NT) orow[j] = logits[j];
}

extern "C" void kernel_launch(void* const* d_in, const int* in_sizes, int n_in,
                              void* d_out, int out_size) {
    (void)n_in; (void)out_size;
    int Bn = in_sizes[0] / CDIM;
    rerank_kernel<<<Bn, NT>>>(
        (const float*)d_in[0],  (const float*)d_in[1],  (const float*)d_in[2],
        (const float*)d_in[3],  (const float*)d_in[4],  (const int*)d_in[5],
        (const int*)d_in[6],    (const int*)d_in[7],    (const float*)d_in[8],
        (const float*)d_in[9],  (const float*)d_in[10], (const float*)d_in[11],
        (const float*)d_in[12], (const float*)d_in[13], (float*)d_out);
}